// round 6
// baseline (speedup 1.0000x reference)
#include <cuda_runtime.h>
#include <math.h>

#define MAXB 8192
#define NS   16
#define NBLK 16
#define TPB  512
#define D128 128
#define MARGIN 0.8f
#define EPS 1e-6f
#define MAXT 4288
#define KH   32
#define AP   132          // smem pitch (floats), 16B-aligned stride (528B)
#define PADSQ 1.0e30f

__device__ int   g_order[MAXB];
__device__ unsigned short g_lrank[MAXB];
__device__ int   g_bhist[NBLK][NS];
__device__ int4  g_tiles[MAXT];
__device__ int   g_T;
__device__ unsigned long long g_bestP[MAXB];
__device__ unsigned long long g_bestN[MAXB];
__device__ float g_blkL[128], g_blkV[128];
__device__ unsigned g_ticket;

__device__ __forceinline__ unsigned mono(float f) {
    unsigned u = __float_as_uint(f);
    return (u & 0x80000000u) ? ~u : (u | 0x80000000u);
}
__device__ __forceinline__ unsigned long long dup2(float a) {
    unsigned long long d;
    asm("mov.b64 %0, {%1, %1};" : "=l"(d) : "f"(a));
    return d;
}
#define FMA2(d, a, b) asm("fma.rn.f32x2 %0, %1, %2, %0;" : "+l"(d) : "l"(a), "l"(b))

// ---------------- K1: per-block histogram + local ranks (no atomics) ----------------
__global__ void __launch_bounds__(TPB) k_hist(const int* __restrict__ sbj, int B) {
    __shared__ int whist[16][NS];
    __shared__ int woff[16][NS];
    const int tid = threadIdx.x, w = tid >> 5, lane = tid & 31;
    const unsigned full = 0xffffffffu;

    for (int j = blockIdx.x * TPB + tid; j < B; j += gridDim.x * TPB) {
        g_bestP[j] = 0ULL; g_bestN[j] = 0ULL;
    }

    int i = blockIdx.x * TPB + tid;
    int s = NS;
    if (i < B) { s = sbj[i]; s = min(max(s, 0), NS - 1); }
    unsigned myMask = 0u; int cnt = 0;
    #pragma unroll
    for (int t = 0; t < NS; t++) {
        unsigned m = __ballot_sync(full, s == t);
        if (s == t) myMask = m;
        if (lane == t) cnt = __popc(m);
    }
    int rankInWarp = __popc(myMask & ((1u << lane) - 1u));
    if (lane < NS) whist[w][lane] = cnt;
    __syncthreads();

    // warp s: exclusive scan of whist[0..15][s]
    {
        int sub = w;
        int v = (lane < 16) ? whist[lane][sub] : 0;
        int inc = v;
        #pragma unroll
        for (int off = 1; off < 16; off <<= 1) {
            int n = __shfl_up_sync(full, inc, off);
            if (lane >= off) inc += n;
        }
        if (lane < 16) woff[lane][sub] = inc - v;
        if (lane == 15) g_bhist[blockIdx.x][sub] = inc;
    }
    __syncthreads();
    if (i < B) g_lrank[i] = (unsigned short)(woff[w][s] + rankInWarp);
}

// ---------------- K2: global scan + scatter + tile list ----------------
__global__ void __launch_bounds__(TPB) k_scatter(const int* __restrict__ sbj, int B) {
    __shared__ int boff[NBLK][NS];
    __shared__ int sbase[NS + 1];
    __shared__ int stot[NS];
    __shared__ int tbase[NS], tnts[NS];
    const int tid = threadIdx.x, w = tid >> 5, lane = tid & 31;
    const unsigned full = 0xffffffffu;

    // warp s: exclusive scan over blocks of g_bhist[b][s]
    {
        int sub = w;
        int v = (lane < NBLK) ? g_bhist[lane][sub] : 0;
        int inc = v;
        #pragma unroll
        for (int off = 1; off < 16; off <<= 1) {
            int n = __shfl_up_sync(full, inc, off);
            if (lane >= off) inc += n;
        }
        if (lane < NBLK) boff[lane][sub] = inc - v;
        if (lane == NBLK - 1) stot[sub] = inc;
    }
    __syncthreads();
    if (w == 0) {
        int len = (lane < NS) ? stot[lane] : 0;
        int inc = len;
        #pragma unroll
        for (int off = 1; off < 16; off <<= 1) {
            int n = __shfl_up_sync(full, inc, off);
            if (lane >= off) inc += n;
        }
        if (lane < NS) sbase[lane] = inc - len;
        if (lane == NS - 1) sbase[NS] = inc;
        int nt = (len + 127) >> 7;
        int ntri = nt * (nt + 1) / 2;
        int inc2 = ntri;
        #pragma unroll
        for (int off = 1; off < 16; off <<= 1) {
            int n = __shfl_up_sync(full, inc2, off);
            if (lane >= off) inc2 += n;
        }
        if (lane < NS) { tbase[lane] = inc2 - ntri; tnts[lane] = nt; }
        if (lane == NS - 1) g_T = inc2;
    }
    __syncthreads();

    int i = blockIdx.x * TPB + tid;
    if (i < B) {
        int s = sbj[i]; s = min(max(s, 0), NS - 1);
        g_order[sbase[s] + boff[blockIdx.x][s] + (int)g_lrank[i]] = i;
    }

    if (blockIdx.x == 0) {
        int nt = tnts[w], lo = sbase[w], hi = sbase[w + 1];
        int ntri = nt * (nt + 1) / 2;
        for (int t = lane; t < ntri; t += 32) {
            int a = 0, rem = t;
            while (rem >= nt - a) { rem -= nt - a; a++; }
            int b = a + rem;
            g_tiles[tbase[w] + t] = make_int4(lo + 128 * a, lo + 128 * b, hi, 0);
        }
    }
}

// ---------------- K3: 128x128 triangle mining, f32x2, smem-atomic selection ----------------
__global__ void __launch_bounds__(256) k_mine(const float* __restrict__ emb,
                                              const int* __restrict__ labels) {
    __shared__ __align__(16) float As[KH * AP];
    __shared__ __align__(16) float Bs[KH * AP];
    __shared__ int   aId[128], aLab[128], bId[128], bLab[128];
    __shared__ float aSq[128], bSq[128];
    __shared__ unsigned long long sPa[128], sNa[128], sPb[128], sNb[128];

    const int tid = threadIdx.x;
    const int tx = tid & 15, ty = tid >> 4;
    const int T = g_T;

    for (int t = blockIdx.x; t < T; t += gridDim.x) {
        const int4 dsc = g_tiles[t];
        const int aBase = dsc.x, bBase = dsc.y, hi = dsc.z;
        const int na = min(128, hi - aBase);
        const int nb = min(128, hi - bBase);

        __syncthreads();   // previous tile fully done with smem
        if (tid < 128) {
            sPa[tid] = 0ULL; sNa[tid] = 0ULL;
            if (tid < na) {
                int i = g_order[aBase + tid];
                aId[tid] = i; aLab[tid] = labels[i]; aSq[tid] = 0.f;
            } else { aId[tid] = -1; aLab[tid] = -2; aSq[tid] = PADSQ; }
        } else {
            int c = tid - 128;
            sPb[c] = 0ULL; sNb[c] = 0ULL;
            if (c < nb) {
                int j = g_order[bBase + c];
                bId[c] = j; bLab[c] = labels[j]; bSq[c] = 0.f;
            } else { bId[c] = -1; bLab[c] = -3; bSq[c] = PADSQ; }
        }

        unsigned long long acc2[8][4];
        #pragma unroll
        for (int r = 0; r < 8; r++)
            #pragma unroll
            for (int c = 0; c < 4; c++) acc2[r][c] = 0ULL;

        for (int kh = 0; kh < D128; kh += KH) {
            __syncthreads();   // ids ready / prior chunk compute done
            // fill: 128 rows x 8 float4 per side; 256 threads x 4 iters
            #pragma unroll
            for (int it = 0; it < 4; it++) {
                int idx = tid + it * 256;
                int r = idx >> 3, kq = idx & 7;
                float4 v = make_float4(0.f, 0.f, 0.f, 0.f);
                float4 u = make_float4(0.f, 0.f, 0.f, 0.f);
                int ia = aId[r], ib = bId[r];
                if (ia >= 0) v = reinterpret_cast<const float4*>(emb + (size_t)ia * D128 + kh)[kq];
                if (ib >= 0) u = reinterpret_cast<const float4*>(emb + (size_t)ib * D128 + kh)[kq];
                int kb = kq * 4;
                As[(kb + 0) * AP + r] = v.x;
                As[(kb + 1) * AP + r] = v.y;
                As[(kb + 2) * AP + r] = v.z;
                As[(kb + 3) * AP + r] = v.w;
                Bs[(kb + 0) * AP + r] = u.x;
                Bs[(kb + 1) * AP + r] = u.y;
                Bs[(kb + 2) * AP + r] = u.z;
                Bs[(kb + 3) * AP + r] = u.w;
            }
            __syncthreads();

            // norms from smem columns (cheap, deterministic)
            if (tid < 128) {
                float s = 0.f;
                #pragma unroll 8
                for (int k = 0; k < KH; k++) { float v = As[k * AP + tid]; s = fmaf(v, v, s); }
                aSq[tid] += s;
            } else {
                int c = tid - 128;
                float s = 0.f;
                #pragma unroll 8
                for (int k = 0; k < KH; k++) { float v = Bs[k * AP + c]; s = fmaf(v, v, s); }
                bSq[c] += s;
            }

            #pragma unroll 4
            for (int k = 0; k < KH; k++) {
                const float4 a0 = *reinterpret_cast<const float4*>(&As[k * AP + 8 * ty]);
                const float4 a1 = *reinterpret_cast<const float4*>(&As[k * AP + 8 * ty + 4]);
                const ulonglong2 b0 = *reinterpret_cast<const ulonglong2*>(&Bs[k * AP + 8 * tx]);
                const ulonglong2 b1 = *reinterpret_cast<const ulonglong2*>(&Bs[k * AP + 8 * tx + 4]);
                unsigned long long aa[8];
                aa[0] = dup2(a0.x); aa[1] = dup2(a0.y); aa[2] = dup2(a0.z); aa[3] = dup2(a0.w);
                aa[4] = dup2(a1.x); aa[5] = dup2(a1.y); aa[6] = dup2(a1.z); aa[7] = dup2(a1.w);
                #pragma unroll
                for (int r = 0; r < 8; r++) {
                    FMA2(acc2[r][0], aa[r], b0.x);
                    FMA2(acc2[r][1], aa[r], b0.y);
                    FMA2(acc2[r][2], aa[r], b1.x);
                    FMA2(acc2[r][3], aa[r], b1.y);
                }
            }
        }
        __syncthreads();   // norms + ids final before selection

        // selection with packed keys (pos: mono<<32|~idx ; neg: ~mono<<32|~idx ; max-combine)
        int myAL[8], myAI[8], myBL[8], myBI[8];
        float myAS[8], myBS[8];
        #pragma unroll
        for (int q = 0; q < 8; q++) {
            int rr = 8 * ty + q, cc = 8 * tx + q;
            myAL[q] = aLab[rr]; myAI[q] = aId[rr]; myAS[q] = aSq[rr];
            myBL[q] = bLab[cc]; myBI[q] = bId[cc]; myBS[q] = bSq[cc];
        }
        unsigned long long colP[8], colN[8];
        #pragma unroll
        for (int q = 0; q < 8; q++) { colP[q] = 0ULL; colN[q] = 0ULL; }

        #pragma unroll
        for (int r = 0; r < 8; r++) {
            float accR[8];
            #pragma unroll
            for (int cp = 0; cp < 4; cp++)
                asm("mov.b64 {%0,%1}, %2;" : "=f"(accR[2 * cp]), "=f"(accR[2 * cp + 1]) : "l"(acc2[r][cp]));
            unsigned long long rowP = 0ULL, rowN = 0ULL;
            #pragma unroll
            for (int c = 0; c < 8; c++) {
                float d2 = myAS[r] + myBS[c] - 2.f * accR[c];
                unsigned m = mono(d2);
                if (myAL[r] == myBL[c]) {
                    if (myAI[r] != myBI[c]) {
                        unsigned long long kr = ((unsigned long long)m << 32) | (unsigned)(~myBI[c]);
                        unsigned long long kc = ((unsigned long long)m << 32) | (unsigned)(~myAI[r]);
                        if (kr > rowP) rowP = kr;
                        if (kc > colP[c]) colP[c] = kc;
                    }
                } else {
                    unsigned long long kr = ((unsigned long long)(~m) << 32) | (unsigned)(~myBI[c]);
                    unsigned long long kc = ((unsigned long long)(~m) << 32) | (unsigned)(~myAI[r]);
                    if (kr > rowN) rowN = kr;
                    if (kc > colN[c]) colN[c] = kc;
                }
            }
            if (rowP) atomicMax(&sPa[8 * ty + r], rowP);
            if (rowN) atomicMax(&sNa[8 * ty + r], rowN);
        }
        #pragma unroll
        for (int c = 0; c < 8; c++) {
            if (colP[c]) atomicMax(&sPb[8 * tx + c], colP[c]);
            if (colN[c]) atomicMax(&sNb[8 * tx + c], colN[c]);
        }
        __syncthreads();

        if (tid < 128) {
            int i = aId[tid];
            if (i >= 0) {
                if (sPa[tid]) atomicMax(&g_bestP[i], sPa[tid]);
                if (sNa[tid]) atomicMax(&g_bestN[i], sNa[tid]);
            }
        } else {
            int c = tid - 128;
            int j = bId[c];
            if (j >= 0) {
                if (sPb[c]) atomicMax(&g_bestP[j], sPb[c]);
                if (sNb[c]) atomicMax(&g_bestN[j], sNb[c]);
            }
        }
    }
}

// ---------------- K4: decode + triplet epilogue + fused final reduction ----------------
__global__ void __launch_bounds__(256) k_merge(const float* __restrict__ emb,
                                               float* __restrict__ out, int B, int nblk) {
    __shared__ float sL[8], sV[8];
    __shared__ bool  lastBlk;
    const int w = threadIdx.x >> 5, lane = threadIdx.x & 31;
    float accL = 0.f, accV = 0.f;

    #pragma unroll
    for (int q = 0; q < 8; q++) {
        int i = (blockIdx.x * 8 + w) * 8 + q;
        if (i >= B) break;
        unsigned long long kp = g_bestP[i];
        unsigned long long kn = g_bestN[i];
        int bpI = kp ? (int)(~(unsigned)kp) : -1;
        int bnI = kn ? (int)(~(unsigned)kn) : -1;
        if (bpI >= 0 && bnI >= 0) {
            const float4 a = reinterpret_cast<const float4*>(emb + (size_t)i   * D128)[lane];
            const float4 p = reinterpret_cast<const float4*>(emb + (size_t)bpI * D128)[lane];
            const float4 n = reinterpret_cast<const float4*>(emb + (size_t)bnI * D128)[lane];
            float dx, sp, sn;
            dx = a.x - p.x + EPS; sp = dx * dx;
            dx = a.y - p.y + EPS; sp = fmaf(dx, dx, sp);
            dx = a.z - p.z + EPS; sp = fmaf(dx, dx, sp);
            dx = a.w - p.w + EPS; sp = fmaf(dx, dx, sp);
            dx = a.x - n.x + EPS; sn = dx * dx;
            dx = a.y - n.y + EPS; sn = fmaf(dx, dx, sn);
            dx = a.z - n.z + EPS; sn = fmaf(dx, dx, sn);
            dx = a.w - n.w + EPS; sn = fmaf(dx, dx, sn);
            #pragma unroll
            for (int off = 16; off > 0; off >>= 1) {
                sp += __shfl_xor_sync(0xffffffff, sp, off);
                sn += __shfl_xor_sync(0xffffffff, sn, off);
            }
            accL += fmaxf(sqrtf(sp) - sqrtf(sn) + MARGIN, 0.f);
            accV += 1.f;
        }
    }
    if (lane == 0) { sL[w] = accL; sV[w] = accV; }
    __syncthreads();
    if (threadIdx.x == 0) {
        float l = 0.f, v = 0.f;
        #pragma unroll
        for (int t = 0; t < 8; t++) { l += sL[t]; v += sV[t]; }
        g_blkL[blockIdx.x] = l;
        g_blkV[blockIdx.x] = v;
        __threadfence();
        lastBlk = (atomicInc(&g_ticket, (unsigned)(nblk - 1)) == (unsigned)(nblk - 1));
    }
    __syncthreads();
    if (lastBlk) {
        __shared__ float rl[128], rv[128];
        int tid = threadIdx.x;
        if (tid < 128) {
            float l = 0.f, v = 0.f;
            for (int b = tid; b < nblk; b += 128) { l += g_blkL[b]; v += g_blkV[b]; }
            rl[tid] = l; rv[tid] = v;
        }
        __syncthreads();
        for (int off = 64; off > 0; off >>= 1) {
            if (tid < off) { rl[tid] += rl[tid + off]; rv[tid] += rv[tid + off]; }
            __syncthreads();
        }
        if (tid == 0) {
            float cnt = rv[0];
            out[0] = (cnt > 0.f) ? (rl[0] / fmaxf(cnt, 1.f)) : 0.f;
        }
    }
}

extern "C" void kernel_launch(void* const* d_in, const int* in_sizes, int n_in,
                              void* d_out, int out_size) {
    const float* emb   = (const float*)d_in[0];
    const int* labels  = (const int*)d_in[1];
    const int* sbj     = (const int*)d_in[2];
    float* out = (float*)d_out;
    int B = in_sizes[1];

    k_hist<<<NBLK, TPB>>>(sbj, B);
    k_scatter<<<NBLK, TPB>>>(sbj, B);
    k_mine<<<296, 256>>>(emb, labels);
    int nblk = (B + 63) / 64;
    k_merge<<<nblk, 256>>>(emb, out, B, nblk);
}

// round 7
// speedup vs baseline: 1.0152x; 1.0152x over previous
#include <cuda_runtime.h>
#include <math.h>

#define NS    16
#define D128  128
#define MARGIN 0.8f
#define EPS   1e-6f
#define GRID  148
#define KH    32
#define AP    132
#define BPP   68
#define MAXB  8192
#define MAXT  2048
#define PADSQ 1.0e30f

__device__ int   g_order[MAXB];
__device__ unsigned short g_lrank[MAXB];
__device__ int   g_bhist[32][NS];
__device__ int4  g_tiles[MAXT];
__device__ int   g_T;
__device__ unsigned long long g_bestP[MAXB];
__device__ unsigned long long g_bestN[MAXB];
__device__ float g_bL[GRID], g_bV[GRID];
__device__ unsigned g_arrive;
__device__ unsigned g_epoch;

__device__ __forceinline__ unsigned mono(float f) {
    unsigned u = __float_as_uint(f);
    return (u & 0x80000000u) ? ~u : (u | 0x80000000u);
}
__device__ __forceinline__ unsigned long long dup2(float a) {
    unsigned long long d;
    asm("mov.b64 %0, {%1, %1};" : "=l"(d) : "f"(a));
    return d;
}
#define FMA2(d, a, b) asm("fma.rn.f32x2 %0, %1, %2, %0;" : "+l"(d) : "l"(a), "l"(b))

__global__ void __launch_bounds__(256) k_all(const float* __restrict__ emb,
                                             const int* __restrict__ labels,
                                             const int* __restrict__ sbj,
                                             float* __restrict__ out, int B) {
    __shared__ __align__(16) float As[KH * AP];
    __shared__ __align__(16) float Bs[KH * BPP];
    __shared__ int   aId[128], aLab[128], bId[64], bLab[64];
    __shared__ float aSq[128], bSq[64];
    __shared__ unsigned long long sPb[64], sNb[64];
    __shared__ int whist[8][NS], woff[8][NS];
    __shared__ int sbase[NS + 1], stot[NS], boffs[NS];
    __shared__ int tb[NS], tn[NS], tm[NS];
    __shared__ float rl[256], rv[256];
    __shared__ float sL[8], sV[8];
    __shared__ unsigned sE0;

    const int tid = threadIdx.x;
    const int w = tid >> 5, lane = tid & 31;
    const int bx = blockIdx.x;
    const unsigned full = 0xffffffffu;
    const int NC = (B + 255) >> 8;
    unsigned nbar = 1;

    if (tid == 0) sE0 = *(volatile unsigned*)&g_epoch;
    __syncthreads();

    // grid barrier (epoch-based; all GRID blocks co-resident)
    #define GBAR() do { \
        __syncthreads(); \
        if (tid == 0) { \
            __threadfence(); \
            unsigned old = atomicAdd(&g_arrive, 1u); \
            if (old == GRID - 1) { g_arrive = 0; __threadfence(); atomicAdd(&g_epoch, 1u); } \
            while (*(volatile unsigned*)&g_epoch - sE0 < nbar) { } \
            __threadfence(); \
        } \
        __syncthreads(); \
        nbar++; \
    } while (0)

    // ---------- phase 0: init bests + per-chunk histogram/ranks ----------
    for (int i = bx * 256 + tid; i < B; i += GRID * 256) { g_bestP[i] = 0ULL; g_bestN[i] = 0ULL; }
    if (bx < NC) {
        int i = bx * 256 + tid;
        int s = NS;
        if (i < B) { s = sbj[i]; s = min(max(s, 0), NS - 1); }
        unsigned myMask = 0u; int cnt = 0;
        #pragma unroll
        for (int t2 = 0; t2 < NS; t2++) {
            unsigned m = __ballot_sync(full, s == t2);
            if (s == t2) myMask = m;
            if (lane == t2) cnt = __popc(m);
        }
        int rIW = __popc(myMask & ((1u << lane) - 1u));
        if (lane < NS) whist[w][lane] = cnt;
        __syncthreads();
        if (tid < NS) {
            int acc = 0;
            #pragma unroll
            for (int w2 = 0; w2 < 8; w2++) { woff[w2][tid] = acc; acc += whist[w2][tid]; }
            g_bhist[bx][tid] = acc;
        }
        __syncthreads();
        if (i < B) g_lrank[i] = (unsigned short)(woff[w][s] + rIW);
    }
    GBAR();

    // ---------- phase 1: global scan + scatter + tile list ----------
    if (bx < NC) {
        if (tid < NS) {
            int acc = 0, myoff = 0;
            for (int b = 0; b < NC; b++) { if (b == bx) myoff = acc; acc += g_bhist[b][tid]; }
            boffs[tid] = myoff; stot[tid] = acc;
        }
        __syncthreads();
        if (tid == 0) {
            int a = 0;
            for (int s = 0; s < NS; s++) { sbase[s] = a; a += stot[s]; }
            sbase[NS] = a;
        }
        __syncthreads();
        int i = bx * 256 + tid;
        if (i < B) {
            int s = sbj[i]; s = min(max(s, 0), NS - 1);
            g_order[sbase[s] + boffs[s] + (int)g_lrank[i]] = i;
        }
        if (bx == 0) {
            if (tid == 0) {
                int acc = 0;
                for (int s = 0; s < NS; s++) {
                    int len = sbase[s + 1] - sbase[s];
                    int nt = (len + 127) >> 7, m = (len + 63) >> 6;
                    tb[s] = acc; tn[s] = nt; tm[s] = m;
                    for (int a2 = 0; a2 < nt; a2++) acc += max(0, m - 2 * a2);
                }
                g_T = acc;
            }
            __syncthreads();
            for (int s = w; s < NS; s += 8) {
                int nt = tn[s], m = tm[s], lo = sbase[s], hi = sbase[s + 1];
                int cnt2 = 0;
                for (int a2 = 0; a2 < nt; a2++) cnt2 += max(0, m - 2 * a2);
                for (int t = lane; t < cnt2; t += 32) {
                    int a2 = 0, rem = t;
                    while (rem >= max(0, m - 2 * a2)) { rem -= max(0, m - 2 * a2); a2++; }
                    int c = 2 * a2 + rem;
                    g_tiles[tb[s] + t] = make_int4(lo + 128 * a2, lo + 64 * c, hi, 0);
                }
            }
        }
    }
    GBAR();

    // ---------- phase 2: mining (128 rows x 64 cols tiles) ----------
    {
        const int tx = tid & 15, ty = tid >> 4;
        const int T = g_T;
        for (int t = bx; t < T; t += GRID) {
            const int4 dsc = g_tiles[t];
            const int aBase = dsc.x, bBase = dsc.y, hi = dsc.z;
            const int na = min(128, hi - aBase);
            const int nb = min(64, hi - bBase);

            __syncthreads();
            if (tid < 128) {
                if (tid < na) { int i = g_order[aBase + tid]; aId[tid] = i; aLab[tid] = labels[i]; aSq[tid] = 0.f; }
                else { aId[tid] = -1; aLab[tid] = -2; aSq[tid] = PADSQ; }
            } else if (tid < 192) {
                int c = tid - 128;
                sPb[c] = 0ULL; sNb[c] = 0ULL;
                if (c < nb) { int j = g_order[bBase + c]; bId[c] = j; bLab[c] = labels[j]; bSq[c] = 0.f; }
                else { bId[c] = -1; bLab[c] = -3; bSq[c] = PADSQ; }
            }

            unsigned long long acc2[8][2];
            #pragma unroll
            for (int r = 0; r < 8; r++) { acc2[r][0] = 0ULL; acc2[r][1] = 0ULL; }

            for (int kh = 0; kh < D128; kh += KH) {
                __syncthreads();
                #pragma unroll
                for (int it = 0; it < 4; it++) {
                    int idx = tid + it * 256;
                    int r = idx >> 3, kq = idx & 7;
                    float4 v = make_float4(0.f, 0.f, 0.f, 0.f);
                    int ia = aId[r];
                    if (ia >= 0) v = reinterpret_cast<const float4*>(emb + (size_t)ia * D128 + kh)[kq];
                    int kb = kq * 4;
                    As[(kb + 0) * AP + r] = v.x;
                    As[(kb + 1) * AP + r] = v.y;
                    As[(kb + 2) * AP + r] = v.z;
                    As[(kb + 3) * AP + r] = v.w;
                }
                #pragma unroll
                for (int it = 0; it < 2; it++) {
                    int idx = tid + it * 256;
                    int r = idx >> 3, kq = idx & 7;
                    float4 u = make_float4(0.f, 0.f, 0.f, 0.f);
                    int ib = bId[r];
                    if (ib >= 0) u = reinterpret_cast<const float4*>(emb + (size_t)ib * D128 + kh)[kq];
                    int kb = kq * 4;
                    Bs[(kb + 0) * BPP + r] = u.x;
                    Bs[(kb + 1) * BPP + r] = u.y;
                    Bs[(kb + 2) * BPP + r] = u.z;
                    Bs[(kb + 3) * BPP + r] = u.w;
                }
                __syncthreads();

                if (tid < 128) {
                    float s = 0.f;
                    #pragma unroll 8
                    for (int k = 0; k < KH; k++) { float v = As[k * AP + tid]; s = fmaf(v, v, s); }
                    aSq[tid] += s;
                } else if (tid < 192) {
                    int c = tid - 128;
                    float s = 0.f;
                    #pragma unroll 8
                    for (int k = 0; k < KH; k++) { float v = Bs[k * BPP + c]; s = fmaf(v, v, s); }
                    bSq[c] += s;
                }

                #pragma unroll 4
                for (int k = 0; k < KH; k++) {
                    const float4 a0 = *reinterpret_cast<const float4*>(&As[k * AP + 8 * ty]);
                    const float4 a1 = *reinterpret_cast<const float4*>(&As[k * AP + 8 * ty + 4]);
                    const ulonglong2 bq = *reinterpret_cast<const ulonglong2*>(&Bs[k * BPP + 4 * tx]);
                    unsigned long long aa[8];
                    aa[0] = dup2(a0.x); aa[1] = dup2(a0.y); aa[2] = dup2(a0.z); aa[3] = dup2(a0.w);
                    aa[4] = dup2(a1.x); aa[5] = dup2(a1.y); aa[6] = dup2(a1.z); aa[7] = dup2(a1.w);
                    #pragma unroll
                    for (int r = 0; r < 8; r++) {
                        FMA2(acc2[r][0], aa[r], bq.x);
                        FMA2(acc2[r][1], aa[r], bq.y);
                    }
                }
            }
            __syncthreads();

            // per-thread B metadata (4 cols)
            int myBI[4], myBL[4]; float myBS[4];
            #pragma unroll
            for (int q = 0; q < 4; q++) {
                int cc = 4 * tx + q;
                myBI[q] = bId[cc]; myBL[q] = bLab[cc]; myBS[q] = bSq[cc];
            }
            unsigned long long colP[4], colN[4];
            #pragma unroll
            for (int q = 0; q < 4; q++) { colP[q] = 0ULL; colN[q] = 0ULL; }

            // per-row selection + in-warp shfl reduction over 16 tx
            #pragma unroll
            for (int r = 0; r < 8; r++) {
                int rr = 8 * ty + r;
                int aI = aId[rr], aL = aLab[rr];
                float aS = aSq[rr];
                float af[2];
                unsigned long long rowP = 0ULL, rowN = 0ULL;
                #pragma unroll
                for (int p = 0; p < 2; p++) {
                    asm("mov.b64 {%0,%1}, %2;" : "=f"(af[0]), "=f"(af[1]) : "l"(acc2[r][p]));
                    #pragma unroll
                    for (int j = 0; j < 2; j++) {
                        int c = 2 * p + j;
                        float d2 = aS + myBS[c] - 2.f * af[j];
                        unsigned m = mono(d2);
                        if (aL == myBL[c]) {
                            if (aI != myBI[c]) {
                                unsigned long long kr = ((unsigned long long)m << 32) | (unsigned)(~myBI[c]);
                                unsigned long long kc = ((unsigned long long)m << 32) | (unsigned)(~aI);
                                if (kr > rowP) rowP = kr;
                                if (kc > colP[c]) colP[c] = kc;
                            }
                        } else {
                            unsigned long long kr = ((unsigned long long)(~m) << 32) | (unsigned)(~myBI[c]);
                            unsigned long long kc = ((unsigned long long)(~m) << 32) | (unsigned)(~aI);
                            if (kr > rowN) rowN = kr;
                            if (kc > colN[c]) colN[c] = kc;
                        }
                    }
                }
                #pragma unroll
                for (int off = 1; off < 16; off <<= 1) {
                    unsigned long long oP = __shfl_xor_sync(full, rowP, off);
                    unsigned long long oN = __shfl_xor_sync(full, rowN, off);
                    if (oP > rowP) rowP = oP;
                    if (oN > rowN) rowN = oN;
                }
                if (tx == 0 && aI >= 0) {
                    if (rowP) atomicMax(&g_bestP[aI], rowP);
                    if (rowN) atomicMax(&g_bestN[aI], rowN);
                }
            }
            // column-side: combine 2 ty-halves in warp, then smem atomics
            #pragma unroll
            for (int q = 0; q < 4; q++) {
                unsigned long long oP = __shfl_xor_sync(full, colP[q], 16);
                unsigned long long oN = __shfl_xor_sync(full, colN[q], 16);
                if (oP > colP[q]) colP[q] = oP;
                if (oN > colN[q]) colN[q] = oN;
            }
            if (lane < 16) {
                #pragma unroll
                for (int q = 0; q < 4; q++) {
                    int cc = 4 * tx + q;
                    if (colP[q]) atomicMax(&sPb[cc], colP[q]);
                    if (colN[q]) atomicMax(&sNb[cc], colN[q]);
                }
            }
            __syncthreads();
            if (tid < 64) {
                int j = bId[tid];
                if (j >= 0) {
                    if (sPb[tid]) atomicMax(&g_bestP[j], sPb[tid]);
                    if (sNb[tid]) atomicMax(&g_bestN[j], sNb[tid]);
                }
            }
        }
    }
    GBAR();

    // ---------- phase 3: decode + triplet epilogue (all warps) ----------
    {
        float accL = 0.f, accV = 0.f;
        for (int i = bx * 8 + w; i < B; i += GRID * 8) {
            unsigned long long kp = g_bestP[i];
            unsigned long long kn = g_bestN[i];
            int bpI = kp ? (int)(~(unsigned)kp) : -1;
            int bnI = kn ? (int)(~(unsigned)kn) : -1;
            if (bpI >= 0 && bnI >= 0) {
                const float4 a = reinterpret_cast<const float4*>(emb + (size_t)i   * D128)[lane];
                const float4 p = reinterpret_cast<const float4*>(emb + (size_t)bpI * D128)[lane];
                const float4 n = reinterpret_cast<const float4*>(emb + (size_t)bnI * D128)[lane];
                float dx, sp, sn;
                dx = a.x - p.x + EPS; sp = dx * dx;
                dx = a.y - p.y + EPS; sp = fmaf(dx, dx, sp);
                dx = a.z - p.z + EPS; sp = fmaf(dx, dx, sp);
                dx = a.w - p.w + EPS; sp = fmaf(dx, dx, sp);
                dx = a.x - n.x + EPS; sn = dx * dx;
                dx = a.y - n.y + EPS; sn = fmaf(dx, dx, sn);
                dx = a.z - n.z + EPS; sn = fmaf(dx, dx, sn);
                dx = a.w - n.w + EPS; sn = fmaf(dx, dx, sn);
                #pragma unroll
                for (int off = 16; off > 0; off >>= 1) {
                    sp += __shfl_xor_sync(full, sp, off);
                    sn += __shfl_xor_sync(full, sn, off);
                }
                accL += fmaxf(sqrtf(sp) - sqrtf(sn) + MARGIN, 0.f);
                accV += 1.f;
            }
        }
        if (lane == 0) { sL[w] = accL; sV[w] = accV; }
        __syncthreads();
        if (tid == 0) {
            float l = 0.f, v = 0.f;
            #pragma unroll
            for (int q = 0; q < 8; q++) { l += sL[q]; v += sV[q]; }
            g_bL[bx] = l; g_bV[bx] = v;
        }
    }
    GBAR();

    // ---------- phase 4: final deterministic reduction (block 0) ----------
    if (bx == 0) {
        rl[tid] = (tid < GRID) ? g_bL[tid] : 0.f;
        rv[tid] = (tid < GRID) ? g_bV[tid] : 0.f;
        __syncthreads();
        for (int off = 128; off > 0; off >>= 1) {
            if (tid < off) { rl[tid] += rl[tid + off]; rv[tid] += rv[tid + off]; }
            __syncthreads();
        }
        if (tid == 0) {
            float cnt = rv[0];
            out[0] = (cnt > 0.f) ? (rl[0] / fmaxf(cnt, 1.f)) : 0.f;
        }
    }
}

extern "C" void kernel_launch(void* const* d_in, const int* in_sizes, int n_in,
                              void* d_out, int out_size) {
    const float* emb   = (const float*)d_in[0];
    const int* labels  = (const int*)d_in[1];
    const int* sbj     = (const int*)d_in[2];
    float* out = (float*)d_out;
    int B = in_sizes[1];

    k_all<<<GRID, 256>>>(emb, labels, sbj, out, B);
}

// round 8
// speedup vs baseline: 1.2306x; 1.2122x over previous
#include <cuda_runtime.h>
#include <math.h>

#define NS    16
#define D128  128
#define MARGIN 0.8f
#define EPS   1e-6f
#define GRID  296
#define KH    32
#define AP    132
#define BPP   68
#define MAXB  8192
#define MAXT  2048
#define PADSQ 1.0e30f

__device__ int   g_order[MAXB];
__device__ unsigned short g_lrank[MAXB];
__device__ int   g_bhist[32][NS];
__device__ int4  g_tiles[MAXT];
__device__ int   g_T;
__device__ unsigned long long g_bestP[MAXB];
__device__ unsigned long long g_bestN[MAXB];
__device__ float g_bL[GRID], g_bV[GRID];
__device__ unsigned g_arrive;
__device__ unsigned g_epoch;

__device__ __forceinline__ unsigned mono(float f) {
    unsigned u = __float_as_uint(f);
    return (u & 0x80000000u) ? ~u : (u | 0x80000000u);
}
__device__ __forceinline__ unsigned long long dup2(float a) {
    unsigned long long d;
    asm("mov.b64 %0, {%1, %1};" : "=l"(d) : "f"(a));
    return d;
}
#define FMA2(d, a, b) asm("fma.rn.f32x2 %0, %1, %2, %0;" : "+l"(d) : "l"(a), "l"(b))

__global__ void __launch_bounds__(256, 2) k_all(const float* __restrict__ emb,
                                                const int* __restrict__ labels,
                                                const int* __restrict__ sbj,
                                                float* __restrict__ out, int B) {
    __shared__ __align__(16) float As[KH * AP];
    __shared__ __align__(16) float Bs[KH * BPP];
    __shared__ int   aId[128], aLab[128], bId[64], bLab[64];
    __shared__ float aSq[128], bSq[64];
    __shared__ unsigned long long sPb[64], sNb[64];
    __shared__ int whist[8][NS], woff[8][NS];
    __shared__ int sbase[NS + 1], stot[NS], boffs[NS];
    __shared__ int tb[NS], tn[NS], tm[NS];
    __shared__ float rl[256], rv[256];
    __shared__ float sL[8], sV[8];
    __shared__ unsigned sE0;

    const int tid = threadIdx.x;
    const int w = tid >> 5, lane = tid & 31;
    const int bx = blockIdx.x;
    const unsigned full = 0xffffffffu;
    const int NC = (B + 255) >> 8;
    unsigned nbar = 1;

    if (tid == 0) sE0 = *(volatile unsigned*)&g_epoch;
    __syncthreads();

    // grid barrier (epoch-based; all GRID blocks co-resident by launch_bounds(256,2))
    #define GBAR() do { \
        __syncthreads(); \
        if (tid == 0) { \
            __threadfence(); \
            unsigned old = atomicAdd(&g_arrive, 1u); \
            if (old == GRID - 1) { g_arrive = 0; __threadfence(); atomicAdd(&g_epoch, 1u); } \
            while (*(volatile unsigned*)&g_epoch - sE0 < nbar) { } \
            __threadfence(); \
        } \
        __syncthreads(); \
        nbar++; \
    } while (0)

    // ---------- phase 0: init bests + per-chunk histogram/ranks ----------
    for (int i = bx * 256 + tid; i < B; i += GRID * 256) { g_bestP[i] = 0ULL; g_bestN[i] = 0ULL; }
    if (bx < NC) {
        int i = bx * 256 + tid;
        int s = NS;
        if (i < B) { s = sbj[i]; s = min(max(s, 0), NS - 1); }
        unsigned myMask = 0u; int cnt = 0;
        #pragma unroll
        for (int t2 = 0; t2 < NS; t2++) {
            unsigned m = __ballot_sync(full, s == t2);
            if (s == t2) myMask = m;
            if (lane == t2) cnt = __popc(m);
        }
        int rIW = __popc(myMask & ((1u << lane) - 1u));
        if (lane < NS) whist[w][lane] = cnt;
        __syncthreads();
        if (tid < NS) {
            int acc = 0;
            #pragma unroll
            for (int w2 = 0; w2 < 8; w2++) { woff[w2][tid] = acc; acc += whist[w2][tid]; }
            g_bhist[bx][tid] = acc;
        }
        __syncthreads();
        if (i < B) g_lrank[i] = (unsigned short)(woff[w][s] + rIW);
    }
    GBAR();

    // ---------- phase 1: global scan + scatter + tile list ----------
    if (bx < NC) {
        if (tid < NS) {
            int acc = 0, myoff = 0;
            for (int b = 0; b < NC; b++) { if (b == bx) myoff = acc; acc += g_bhist[b][tid]; }
            boffs[tid] = myoff; stot[tid] = acc;
        }
        __syncthreads();
        if (tid == 0) {
            int a = 0;
            for (int s = 0; s < NS; s++) { sbase[s] = a; a += stot[s]; }
            sbase[NS] = a;
        }
        __syncthreads();
        int i = bx * 256 + tid;
        if (i < B) {
            int s = sbj[i]; s = min(max(s, 0), NS - 1);
            g_order[sbase[s] + boffs[s] + (int)g_lrank[i]] = i;
        }
        if (bx == 0) {
            if (tid == 0) {
                int acc = 0;
                for (int s = 0; s < NS; s++) {
                    int len = sbase[s + 1] - sbase[s];
                    int nt = (len + 127) >> 7, m = (len + 63) >> 6;
                    tb[s] = acc; tn[s] = nt; tm[s] = m;
                    for (int a2 = 0; a2 < nt; a2++) acc += max(0, m - 2 * a2);
                }
                g_T = acc;
            }
            __syncthreads();
            for (int s = w; s < NS; s += 8) {
                int nt = tn[s], m = tm[s], lo = sbase[s], hi = sbase[s + 1];
                int cnt2 = 0;
                for (int a2 = 0; a2 < nt; a2++) cnt2 += max(0, m - 2 * a2);
                for (int t = lane; t < cnt2; t += 32) {
                    int a2 = 0, rem = t;
                    while (rem >= max(0, m - 2 * a2)) { rem -= max(0, m - 2 * a2); a2++; }
                    int c = 2 * a2 + rem;
                    g_tiles[tb[s] + t] = make_int4(lo + 128 * a2, lo + 64 * c, hi, 0);
                }
            }
        }
    }
    GBAR();

    // ---------- phase 2: mining (128 rows x 64 cols tiles) ----------
    {
        const int tx = tid & 15, ty = tid >> 4;
        const int T = g_T;
        for (int t = bx; t < T; t += GRID) {
            const int4 dsc = g_tiles[t];
            const int aBase = dsc.x, bBase = dsc.y, hi = dsc.z;
            const int na = min(128, hi - aBase);
            const int nb = min(64, hi - bBase);

            __syncthreads();
            if (tid < 128) {
                if (tid < na) { int i = g_order[aBase + tid]; aId[tid] = i; aLab[tid] = labels[i]; aSq[tid] = 0.f; }
                else { aId[tid] = -1; aLab[tid] = -2; aSq[tid] = PADSQ; }
            } else if (tid < 192) {
                int c = tid - 128;
                sPb[c] = 0ULL; sNb[c] = 0ULL;
                if (c < nb) { int j = g_order[bBase + c]; bId[c] = j; bLab[c] = labels[j]; bSq[c] = 0.f; }
                else { bId[c] = -1; bLab[c] = -3; bSq[c] = PADSQ; }
            }

            unsigned long long acc2[8][2];
            #pragma unroll
            for (int r = 0; r < 8; r++) { acc2[r][0] = 0ULL; acc2[r][1] = 0ULL; }

            for (int kh = 0; kh < D128; kh += KH) {
                __syncthreads();
                #pragma unroll
                for (int it = 0; it < 4; it++) {
                    int idx = tid + it * 256;
                    int r = idx >> 3, kq = idx & 7;
                    float4 v = make_float4(0.f, 0.f, 0.f, 0.f);
                    int ia = aId[r];
                    if (ia >= 0) v = reinterpret_cast<const float4*>(emb + (size_t)ia * D128 + kh)[kq];
                    int kb = kq * 4;
                    As[(kb + 0) * AP + r] = v.x;
                    As[(kb + 1) * AP + r] = v.y;
                    As[(kb + 2) * AP + r] = v.z;
                    As[(kb + 3) * AP + r] = v.w;
                }
                #pragma unroll
                for (int it = 0; it < 2; it++) {
                    int idx = tid + it * 256;
                    int r = idx >> 3, kq = idx & 7;
                    float4 u = make_float4(0.f, 0.f, 0.f, 0.f);
                    int ib = bId[r];
                    if (ib >= 0) u = reinterpret_cast<const float4*>(emb + (size_t)ib * D128 + kh)[kq];
                    int kb = kq * 4;
                    Bs[(kb + 0) * BPP + r] = u.x;
                    Bs[(kb + 1) * BPP + r] = u.y;
                    Bs[(kb + 2) * BPP + r] = u.z;
                    Bs[(kb + 3) * BPP + r] = u.w;
                }
                __syncthreads();

                if (tid < 128) {
                    float s = 0.f;
                    #pragma unroll 8
                    for (int k = 0; k < KH; k++) { float v = As[k * AP + tid]; s = fmaf(v, v, s); }
                    aSq[tid] += s;
                } else if (tid < 192) {
                    int c = tid - 128;
                    float s = 0.f;
                    #pragma unroll 8
                    for (int k = 0; k < KH; k++) { float v = Bs[k * BPP + c]; s = fmaf(v, v, s); }
                    bSq[c] += s;
                }

                #pragma unroll 4
                for (int k = 0; k < KH; k++) {
                    const float4 a0 = *reinterpret_cast<const float4*>(&As[k * AP + 8 * ty]);
                    const float4 a1 = *reinterpret_cast<const float4*>(&As[k * AP + 8 * ty + 4]);
                    const ulonglong2 bq = *reinterpret_cast<const ulonglong2*>(&Bs[k * BPP + 4 * tx]);
                    unsigned long long aa[8];
                    aa[0] = dup2(a0.x); aa[1] = dup2(a0.y); aa[2] = dup2(a0.z); aa[3] = dup2(a0.w);
                    aa[4] = dup2(a1.x); aa[5] = dup2(a1.y); aa[6] = dup2(a1.z); aa[7] = dup2(a1.w);
                    #pragma unroll
                    for (int r = 0; r < 8; r++) {
                        FMA2(acc2[r][0], aa[r], bq.x);
                        FMA2(acc2[r][1], aa[r], bq.y);
                    }
                }
            }
            __syncthreads();

            // per-thread B metadata (4 cols)
            int myBI[4], myBL[4]; float myBS[4];
            #pragma unroll
            for (int q = 0; q < 4; q++) {
                int cc = 4 * tx + q;
                myBI[q] = bId[cc]; myBL[q] = bLab[cc]; myBS[q] = bSq[cc];
            }
            unsigned long long colP[4], colN[4];
            #pragma unroll
            for (int q = 0; q < 4; q++) { colP[q] = 0ULL; colN[q] = 0ULL; }

            // per-row selection + in-warp shfl reduction over 16 tx
            #pragma unroll
            for (int r = 0; r < 8; r++) {
                int rr = 8 * ty + r;
                int aI = aId[rr], aL = aLab[rr];
                float aS = aSq[rr];
                float af[2];
                unsigned long long rowP = 0ULL, rowN = 0ULL;
                #pragma unroll
                for (int p = 0; p < 2; p++) {
                    asm("mov.b64 {%0,%1}, %2;" : "=f"(af[0]), "=f"(af[1]) : "l"(acc2[r][p]));
                    #pragma unroll
                    for (int j = 0; j < 2; j++) {
                        int c = 2 * p + j;
                        float d2 = aS + myBS[c] - 2.f * af[j];
                        unsigned m = mono(d2);
                        if (aL == myBL[c]) {
                            if (aI != myBI[c]) {
                                unsigned long long kr = ((unsigned long long)m << 32) | (unsigned)(~myBI[c]);
                                unsigned long long kc = ((unsigned long long)m << 32) | (unsigned)(~aI);
                                if (kr > rowP) rowP = kr;
                                if (kc > colP[c]) colP[c] = kc;
                            }
                        } else {
                            unsigned long long kr = ((unsigned long long)(~m) << 32) | (unsigned)(~myBI[c]);
                            unsigned long long kc = ((unsigned long long)(~m) << 32) | (unsigned)(~aI);
                            if (kr > rowN) rowN = kr;
                            if (kc > colN[c]) colN[c] = kc;
                        }
                    }
                }
                #pragma unroll
                for (int off = 1; off < 16; off <<= 1) {
                    unsigned long long oP = __shfl_xor_sync(full, rowP, off);
                    unsigned long long oN = __shfl_xor_sync(full, rowN, off);
                    if (oP > rowP) rowP = oP;
                    if (oN > rowN) rowN = oN;
                }
                if (tx == 0 && aI >= 0) {
                    if (rowP) atomicMax(&g_bestP[aI], rowP);
                    if (rowN) atomicMax(&g_bestN[aI], rowN);
                }
            }
            // column-side: combine 2 ty-halves in warp, then smem atomics
            #pragma unroll
            for (int q = 0; q < 4; q++) {
                unsigned long long oP = __shfl_xor_sync(full, colP[q], 16);
                unsigned long long oN = __shfl_xor_sync(full, colN[q], 16);
                if (oP > colP[q]) colP[q] = oP;
                if (oN > colN[q]) colN[q] = oN;
            }
            if (lane < 16) {
                #pragma unroll
                for (int q = 0; q < 4; q++) {
                    int cc = 4 * tx + q;
                    if (colP[q]) atomicMax(&sPb[cc], colP[q]);
                    if (colN[q]) atomicMax(&sNb[cc], colN[q]);
                }
            }
            __syncthreads();
            if (tid < 64) {
                int j = bId[tid];
                if (j >= 0) {
                    if (sPb[tid]) atomicMax(&g_bestP[j], sPb[tid]);
                    if (sNb[tid]) atomicMax(&g_bestN[j], sNb[tid]);
                }
            }
        }
    }
    GBAR();

    // ---------- phase 3: decode + triplet epilogue (all warps) ----------
    {
        float accL = 0.f, accV = 0.f;
        for (int i = bx * 8 + w; i < B; i += GRID * 8) {
            unsigned long long kp = g_bestP[i];
            unsigned long long kn = g_bestN[i];
            int bpI = kp ? (int)(~(unsigned)kp) : -1;
            int bnI = kn ? (int)(~(unsigned)kn) : -1;
            if (bpI >= 0 && bnI >= 0) {
                const float4 a = reinterpret_cast<const float4*>(emb + (size_t)i   * D128)[lane];
                const float4 p = reinterpret_cast<const float4*>(emb + (size_t)bpI * D128)[lane];
                const float4 n = reinterpret_cast<const float4*>(emb + (size_t)bnI * D128)[lane];
                float dx, sp, sn;
                dx = a.x - p.x + EPS; sp = dx * dx;
                dx = a.y - p.y + EPS; sp = fmaf(dx, dx, sp);
                dx = a.z - p.z + EPS; sp = fmaf(dx, dx, sp);
                dx = a.w - p.w + EPS; sp = fmaf(dx, dx, sp);
                dx = a.x - n.x + EPS; sn = dx * dx;
                dx = a.y - n.y + EPS; sn = fmaf(dx, dx, sn);
                dx = a.z - n.z + EPS; sn = fmaf(dx, dx, sn);
                dx = a.w - n.w + EPS; sn = fmaf(dx, dx, sn);
                #pragma unroll
                for (int off = 16; off > 0; off >>= 1) {
                    sp += __shfl_xor_sync(full, sp, off);
                    sn += __shfl_xor_sync(full, sn, off);
                }
                accL += fmaxf(sqrtf(sp) - sqrtf(sn) + MARGIN, 0.f);
                accV += 1.f;
            }
        }
        if (lane == 0) { sL[w] = accL; sV[w] = accV; }
        __syncthreads();
        if (tid == 0) {
            float l = 0.f, v = 0.f;
            #pragma unroll
            for (int q = 0; q < 8; q++) { l += sL[q]; v += sV[q]; }
            g_bL[bx] = l; g_bV[bx] = v;
        }
    }
    GBAR();

    // ---------- phase 4: final deterministic reduction (block 0) ----------
    if (bx == 0) {
        float l = 0.f, v = 0.f;
        for (int b = tid; b < GRID; b += 256) { l += g_bL[b]; v += g_bV[b]; }
        rl[tid] = l; rv[tid] = v;
        __syncthreads();
        for (int off = 128; off > 0; off >>= 1) {
            if (tid < off) { rl[tid] += rl[tid + off]; rv[tid] += rv[tid + off]; }
            __syncthreads();
        }
        if (tid == 0) {
            float cnt = rv[0];
            out[0] = (cnt > 0.f) ? (rl[0] / fmaxf(cnt, 1.f)) : 0.f;
        }
    }
}

extern "C" void kernel_launch(void* const* d_in, const int* in_sizes, int n_in,
                              void* d_out, int out_size) {
    const float* emb   = (const float*)d_in[0];
    const int* labels  = (const int*)d_in[1];
    const int* sbj     = (const int*)d_in[2];
    float* out = (float*)d_out;
    int B = in_sizes[1];

    k_all<<<GRID, 256>>>(emb, labels, sbj, out, B);
}

// round 10
// speedup vs baseline: 1.3432x; 1.0915x over previous
#include <cuda_runtime.h>
#include <math.h>

#define NS    16
#define D128  128
#define MARGIN 0.8f
#define EPS   1e-6f
#define GRID  444
#define KH    64
#define AP    68
#define MAXB  8192
#define MAXT  8512
#define PADSQ 1.0e30f

__device__ int   g_order[MAXB];
__device__ int   g_bhist[32][NS];
__device__ int4  g_tiles[MAXT];
__device__ int   g_T;
__device__ unsigned long long g_bestP[MAXB];
__device__ unsigned long long g_bestN[MAXB];
__device__ float g_bL[GRID], g_bV[GRID];
__device__ unsigned g_arrive;
__device__ unsigned g_epoch;

__device__ __forceinline__ unsigned mono(float f) {
    unsigned u = __float_as_uint(f);
    return (u & 0x80000000u) ? ~u : (u | 0x80000000u);
}
__device__ __forceinline__ unsigned long long dup2(float a) {
    unsigned long long d;
    asm("mov.b64 %0, {%1, %1};" : "=l"(d) : "f"(a));
    return d;
}
#define FMA2(d, a, b) asm("fma.rn.f32x2 %0, %1, %2, %0;" : "+l"(d) : "l"(a), "l"(b))

__global__ void __launch_bounds__(256, 3) k_all(const float* __restrict__ emb,
                                                const int* __restrict__ labels,
                                                const int* __restrict__ sbj,
                                                float* __restrict__ out, int B) {
    __shared__ __align__(16) float As[KH * AP];
    __shared__ __align__(16) float Bs[KH * AP];
    __shared__ int   aId[64], aLab[64], bId[64], bLab[64];
    __shared__ float aSq[64], bSq[64];
    __shared__ unsigned long long sPb[64], sNb[64];
    __shared__ int whist[8][NS], woff[8][NS];
    __shared__ int sbase[NS + 1], stot[NS], boffs[NS];
    __shared__ int tb[NS], tn[NS];
    __shared__ float rl[256], rv[256];
    __shared__ float sL[8], sV[8];
    __shared__ unsigned sE0;

    const int tid = threadIdx.x;
    const int w = tid >> 5, lane = tid & 31;
    const int bx = blockIdx.x;
    const unsigned full = 0xffffffffu;
    const int NC = (B + 255) >> 8;
    unsigned nbar = 1;

    if (tid == 0) sE0 = *(volatile unsigned*)&g_epoch;
    __syncthreads();

    #define GBAR() do { \
        __syncthreads(); \
        if (tid == 0) { \
            __threadfence(); \
            unsigned old = atomicAdd(&g_arrive, 1u); \
            if (old == GRID - 1) { g_arrive = 0; __threadfence(); atomicAdd(&g_epoch, 1u); } \
            while (*(volatile unsigned*)&g_epoch - sE0 < nbar) { } \
            __threadfence(); \
        } \
        __syncthreads(); \
        nbar++; \
    } while (0)

    // ---------- phase 0: init bests + per-chunk histogram/ranks ----------
    for (int i = bx * 256 + tid; i < B; i += GRID * 256) { g_bestP[i] = 0ULL; g_bestN[i] = 0ULL; }
    int myRank = 0, myS = NS;
    if (bx < NC) {
        int i = bx * 256 + tid;
        if (i < B) { myS = sbj[i]; myS = min(max(myS, 0), NS - 1); }
        unsigned myMask = 0u; int cnt = 0;
        #pragma unroll
        for (int t2 = 0; t2 < NS; t2++) {
            unsigned m = __ballot_sync(full, myS == t2);
            if (myS == t2) myMask = m;
            if (lane == t2) cnt = __popc(m);
        }
        int rIW = __popc(myMask & ((1u << lane) - 1u));
        if (lane < NS) whist[w][lane] = cnt;
        __syncthreads();
        if (tid < NS) {
            int acc = 0;
            #pragma unroll
            for (int w2 = 0; w2 < 8; w2++) { woff[w2][tid] = acc; acc += whist[w2][tid]; }
            g_bhist[bx][tid] = acc;
        }
        __syncthreads();
        if (i < B && myS < NS) myRank = woff[w][myS] + rIW;
    }
    GBAR();

    // ---------- phase 1: global scan + scatter + tile list ----------
    if (bx < NC) {
        if (tid < NS) {
            int acc = 0, myoff = 0;
            for (int b = 0; b < NC; b++) { if (b == bx) myoff = acc; acc += g_bhist[b][tid]; }
            boffs[tid] = myoff; stot[tid] = acc;
        }
        __syncthreads();
        if (tid == 0) {
            int a = 0;
            for (int s = 0; s < NS; s++) { sbase[s] = a; a += stot[s]; }
            sbase[NS] = a;
        }
        __syncthreads();
        int i = bx * 256 + tid;
        if (i < B && myS < NS)
            g_order[sbase[myS] + boffs[myS] + myRank] = i;
        if (bx == 0) {
            if (tid == 0) {
                int acc = 0;
                for (int s = 0; s < NS; s++) {
                    int len = sbase[s + 1] - sbase[s];
                    int m = (len + 63) >> 6;
                    tb[s] = acc; tn[s] = m;
                    acc += m * (m + 1) / 2;
                }
                g_T = acc;
            }
            __syncthreads();
            for (int s = w; s < NS; s += 8) {
                int m = tn[s], lo = sbase[s], hi = sbase[s + 1];
                int ntri = m * (m + 1) / 2;
                for (int t = lane; t < ntri; t += 32) {
                    int a2 = 0, rem = t;
                    while (rem >= m - a2) { rem -= m - a2; a2++; }
                    int b2 = a2 + rem;
                    g_tiles[tb[s] + t] = make_int4(lo + 64 * a2, lo + 64 * b2, hi, 0);
                }
            }
        }
    }
    GBAR();

    // ---------- phase 2: mining (64x64 tiles, full triangle) ----------
    {
        const int tx = tid & 15, ty = tid >> 4;
        const int T = g_T;
        for (int t = bx; t < T; t += GRID) {
            const int4 dsc = g_tiles[t];
            const int aBase = dsc.x, bBase = dsc.y, hi = dsc.z;
            const int na = min(64, hi - aBase);
            const int nb = min(64, hi - bBase);

            __syncthreads();   // previous tile fully consumed
            if (tid < 64) {
                if (tid < na) { int i = g_order[aBase + tid]; aId[tid] = i; aLab[tid] = labels[i]; aSq[tid] = 0.f; }
                else { aId[tid] = -1; aLab[tid] = -2; aSq[tid] = PADSQ; }
            } else if (tid < 128) {
                int c = tid - 64;
                if (c < nb) { int j = g_order[bBase + c]; bId[c] = j; bLab[c] = labels[j]; bSq[c] = 0.f; }
                else { bId[c] = -1; bLab[c] = -3; bSq[c] = PADSQ; }
            } else if (tid < 192) {
                sPb[tid - 128] = 0ULL;
            } else {
                sNb[tid - 192] = 0ULL;
            }

            unsigned long long acc2[4][2];
            #pragma unroll
            for (int r = 0; r < 4; r++) { acc2[r][0] = 0ULL; acc2[r][1] = 0ULL; }

            for (int kh = 0; kh < D128; kh += KH) {
                __syncthreads();   // meta ready / prior chunk consumed
                // fill: lanes vary row (conflict-free scalar stores); kq = float4 idx 0..15
                #pragma unroll
                for (int it = 0; it < 4; it++) {
                    int idx = tid + it * 256;
                    int r = idx & 63, kq = idx >> 6;
                    float4 v = make_float4(0.f, 0.f, 0.f, 0.f);
                    float4 u = make_float4(0.f, 0.f, 0.f, 0.f);
                    int ia = aId[r], ib = bId[r];
                    if (ia >= 0) v = reinterpret_cast<const float4*>(emb + (size_t)ia * D128 + kh)[kq];
                    if (ib >= 0) u = reinterpret_cast<const float4*>(emb + (size_t)ib * D128 + kh)[kq];
                    int kb = kq * 4;
                    As[(kb + 0) * AP + r] = v.x;
                    As[(kb + 1) * AP + r] = v.y;
                    As[(kb + 2) * AP + r] = v.z;
                    As[(kb + 3) * AP + r] = v.w;
                    Bs[(kb + 0) * AP + r] = u.x;
                    Bs[(kb + 1) * AP + r] = u.y;
                    Bs[(kb + 2) * AP + r] = u.z;
                    Bs[(kb + 3) * AP + r] = u.w;
                }
                __syncthreads();

                // norms (warps 0-3) — overlaps the FMA loop of warps 4-7
                if (tid < 64) {
                    float s0 = 0.f, s1 = 0.f, s2 = 0.f, s3 = 0.f;
                    #pragma unroll
                    for (int k = 0; k < KH; k += 4) {
                        float v0 = As[(k + 0) * AP + tid]; s0 = fmaf(v0, v0, s0);
                        float v1 = As[(k + 1) * AP + tid]; s1 = fmaf(v1, v1, s1);
                        float v2 = As[(k + 2) * AP + tid]; s2 = fmaf(v2, v2, s2);
                        float v3 = As[(k + 3) * AP + tid]; s3 = fmaf(v3, v3, s3);
                    }
                    if (aId[tid] >= 0) aSq[tid] += (s0 + s1) + (s2 + s3);
                } else if (tid < 128) {
                    int c = tid - 64;
                    float s0 = 0.f, s1 = 0.f, s2 = 0.f, s3 = 0.f;
                    #pragma unroll
                    for (int k = 0; k < KH; k += 4) {
                        float v0 = Bs[(k + 0) * AP + c]; s0 = fmaf(v0, v0, s0);
                        float v1 = Bs[(k + 1) * AP + c]; s1 = fmaf(v1, v1, s1);
                        float v2 = Bs[(k + 2) * AP + c]; s2 = fmaf(v2, v2, s2);
                        float v3 = Bs[(k + 3) * AP + c]; s3 = fmaf(v3, v3, s3);
                    }
                    if (bId[c] >= 0) bSq[c] += (s0 + s1) + (s2 + s3);
                }

                #pragma unroll 8
                for (int k = 0; k < KH; k++) {
                    const float4 a0 = *reinterpret_cast<const float4*>(&As[k * AP + 4 * ty]);
                    const ulonglong2 bq = *reinterpret_cast<const ulonglong2*>(&Bs[k * AP + 4 * tx]);
                    unsigned long long aa0 = dup2(a0.x), aa1 = dup2(a0.y);
                    unsigned long long aa2 = dup2(a0.z), aa3 = dup2(a0.w);
                    FMA2(acc2[0][0], aa0, bq.x); FMA2(acc2[0][1], aa0, bq.y);
                    FMA2(acc2[1][0], aa1, bq.x); FMA2(acc2[1][1], aa1, bq.y);
                    FMA2(acc2[2][0], aa2, bq.x); FMA2(acc2[2][1], aa2, bq.y);
                    FMA2(acc2[3][0], aa3, bq.x); FMA2(acc2[3][1], aa3, bq.y);
                }
            }
            __syncthreads();   // norms final before selection

            int myBI[4], myBL[4]; float myBS[4];
            #pragma unroll
            for (int q = 0; q < 4; q++) {
                int cc = 4 * tx + q;
                myBI[q] = bId[cc]; myBL[q] = bLab[cc]; myBS[q] = bSq[cc];
            }
            unsigned long long colP[4], colN[4];
            #pragma unroll
            for (int q = 0; q < 4; q++) { colP[q] = 0ULL; colN[q] = 0ULL; }

            #pragma unroll
            for (int r = 0; r < 4; r++) {
                int rr = 4 * ty + r;
                int aI = aId[rr], aL = aLab[rr];
                float aS = aSq[rr];
                float af[2];
                unsigned long long rowP = 0ULL, rowN = 0ULL;
                #pragma unroll
                for (int p = 0; p < 2; p++) {
                    asm("mov.b64 {%0,%1}, %2;" : "=f"(af[0]), "=f"(af[1]) : "l"(acc2[r][p]));
                    #pragma unroll
                    for (int j = 0; j < 2; j++) {
                        int c = 2 * p + j;
                        float d2 = aS + myBS[c] - 2.f * af[j];
                        unsigned m = mono(d2);
                        if (aL == myBL[c]) {
                            if (aI != myBI[c]) {
                                unsigned long long kr = ((unsigned long long)m << 32) | (unsigned)(~myBI[c]);
                                unsigned long long kc = ((unsigned long long)m << 32) | (unsigned)(~aI);
                                if (kr > rowP) rowP = kr;
                                if (kc > colP[c]) colP[c] = kc;
                            }
                        } else {
                            unsigned long long kr = ((unsigned long long)(~m) << 32) | (unsigned)(~myBI[c]);
                            unsigned long long kc = ((unsigned long long)(~m) << 32) | (unsigned)(~aI);
                            if (kr > rowN) rowN = kr;
                            if (kc > colN[c]) colN[c] = kc;
                        }
                    }
                }
                // reduce across 16 tx (stays within half-warp)
                #pragma unroll
                for (int off = 1; off < 16; off <<= 1) {
                    unsigned long long oP = __shfl_xor_sync(full, rowP, off);
                    unsigned long long oN = __shfl_xor_sync(full, rowN, off);
                    if (oP > rowP) rowP = oP;
                    if (oN > rowN) rowN = oN;
                }
                if (tx == 0 && aI >= 0) {
                    if (rowP) atomicMax(&g_bestP[aI], rowP);
                    if (rowN) atomicMax(&g_bestN[aI], rowN);
                }
            }
            // col-side: combine the two ty values in this warp, then smem atomics
            #pragma unroll
            for (int q = 0; q < 4; q++) {
                unsigned long long oP = __shfl_xor_sync(full, colP[q], 16);
                unsigned long long oN = __shfl_xor_sync(full, colN[q], 16);
                if (oP > colP[q]) colP[q] = oP;
                if (oN > colN[q]) colN[q] = oN;
            }
            if (lane < 16) {
                #pragma unroll
                for (int q = 0; q < 4; q++) {
                    int cc = 4 * tx + q;
                    if (colP[q]) atomicMax(&sPb[cc], colP[q]);
                    if (colN[q]) atomicMax(&sNb[cc], colN[q]);
                }
            }
            __syncthreads();
            if (tid < 64) {
                int j = bId[tid];
                if (j >= 0) {
                    if (sPb[tid]) atomicMax(&g_bestP[j], sPb[tid]);
                    if (sNb[tid]) atomicMax(&g_bestN[j], sNb[tid]);
                }
            }
        }
    }
    GBAR();

    // ---------- phase 3: decode + triplet epilogue (all warps) ----------
    {
        float accL = 0.f, accV = 0.f;
        for (int i = bx * 8 + w; i < B; i += GRID * 8) {
            unsigned long long kp = g_bestP[i];
            unsigned long long kn = g_bestN[i];
            int bpI = kp ? (int)(~(unsigned)kp) : -1;
            int bnI = kn ? (int)(~(unsigned)kn) : -1;
            if (bpI >= 0 && bnI >= 0) {
                const float4 a = reinterpret_cast<const float4*>(emb + (size_t)i   * D128)[lane];
                const float4 p = reinterpret_cast<const float4*>(emb + (size_t)bpI * D128)[lane];
                const float4 n = reinterpret_cast<const float4*>(emb + (size_t)bnI * D128)[lane];
                float dx, sp, sn;
                dx = a.x - p.x + EPS; sp = dx * dx;
                dx = a.y - p.y + EPS; sp = fmaf(dx, dx, sp);
                dx = a.z - p.z + EPS; sp = fmaf(dx, dx, sp);
                dx = a.w - p.w + EPS; sp = fmaf(dx, dx, sp);
                dx = a.x - n.x + EPS; sn = dx * dx;
                dx = a.y - n.y + EPS; sn = fmaf(dx, dx, sn);
                dx = a.z - n.z + EPS; sn = fmaf(dx, dx, sn);
                dx = a.w - n.w + EPS; sn = fmaf(dx, dx, sn);
                #pragma unroll
                for (int off = 16; off > 0; off >>= 1) {
                    sp += __shfl_xor_sync(full, sp, off);
                    sn += __shfl_xor_sync(full, sn, off);
                }
                accL += fmaxf(sqrtf(sp) - sqrtf(sn) + MARGIN, 0.f);
                accV += 1.f;
            }
        }
        if (lane == 0) { sL[w] = accL; sV[w] = accV; }
        __syncthreads();
        if (tid == 0) {
            float l = 0.f, v = 0.f;
            #pragma unroll
            for (int q = 0; q < 8; q++) { l += sL[q]; v += sV[q]; }
            g_bL[bx] = l; g_bV[bx] = v;
        }
    }
    GBAR();

    // ---------- phase 4: final deterministic reduction (block 0) ----------
    if (bx == 0) {
        float l = 0.f, v = 0.f;
        for (int b = tid; b < GRID; b += 256) { l += g_bL[b]; v += g_bV[b]; }
        rl[tid] = l; rv[tid] = v;
        __syncthreads();
        for (int off = 128; off > 0; off >>= 1) {
            if (tid < off) { rl[tid] += rl[tid + off]; rv[tid] += rv[tid + off]; }
            __syncthreads();
        }
        if (tid == 0) {
            float cnt = rv[0];
            out[0] = (cnt > 0.f) ? (rl[0] / fmaxf(cnt, 1.f)) : 0.f;
        }
    }
}

extern "C" void kernel_launch(void* const* d_in, const int* in_sizes, int n_in,
                              void* d_out, int out_size) {
    const float* emb   = (const float*)d_in[0];
    const int* labels  = (const int*)d_in[1];
    const int* sbj     = (const int*)d_in[2];
    float* out = (float*)d_out;
    int B = in_sizes[1];

    k_all<<<GRID, 256>>>(emb, labels, sbj, out, B);
}

// round 12
// speedup vs baseline: 1.3653x; 1.0164x over previous
#include <cuda_runtime.h>
#include <math.h>

#define NS    16
#define D128  128
#define MARGIN 0.8f
#define EPS   1e-6f
#define GRID  592
#define KH    64
#define AP    68
#define MAXB  8192
#define MAXT  8512
#define PADSQ 1.0e30f

__device__ int   g_order[MAXB];
__device__ int   g_bhist[32][NS];
__device__ int4  g_tiles[MAXT];
__device__ int   g_T;
__device__ unsigned long long g_bestP[MAXB];
__device__ unsigned long long g_bestN[MAXB];
__device__ float g_bL[GRID], g_bV[GRID];
__device__ unsigned g_arrive;
__device__ unsigned g_epoch;

__device__ __forceinline__ unsigned mono(float f) {
    unsigned u = __float_as_uint(f);
    return (u & 0x80000000u) ? ~u : (u | 0x80000000u);
}
__device__ __forceinline__ unsigned long long dup2(float a) {
    unsigned long long d;
    asm("mov.b64 %0, {%1, %1};" : "=l"(d) : "f"(a));
    return d;
}
#define FMA2(d, a, b) asm("fma.rn.f32x2 %0, %1, %2, %0;" : "+l"(d) : "l"(a), "l"(b))

__global__ void __launch_bounds__(256, 4) k_all(const float* __restrict__ emb,
                                                const int* __restrict__ labels,
                                                const int* __restrict__ sbj,
                                                float* __restrict__ out, int B) {
    __shared__ __align__(16) float As[KH * AP];
    __shared__ __align__(16) float Bs[KH * AP];
    __shared__ int   aId[64], aLab[64], bId[64], bLab[64];
    __shared__ float aSq[64], bSq[64];
    __shared__ unsigned long long sPb[64], sNb[64];
    __shared__ int whist[8][NS], woff[8][NS];
    __shared__ int sbase[NS + 1], stot[NS], boffs[NS];
    __shared__ int tb[NS], tn[NS];
    __shared__ float rl[256], rv[256];
    __shared__ float sL[8], sV[8];
    __shared__ unsigned sE0;

    const int tid = threadIdx.x;
    const int w = tid >> 5, lane = tid & 31;
    const int bx = blockIdx.x;
    const unsigned full = 0xffffffffu;
    const int NC = (B + 255) >> 8;
    unsigned nbar = 1;

    if (tid == 0) sE0 = *(volatile unsigned*)&g_epoch;
    __syncthreads();

    #define GBAR() do { \
        __syncthreads(); \
        if (tid == 0) { \
            __threadfence(); \
            unsigned old = atomicAdd(&g_arrive, 1u); \
            if (old == GRID - 1) { g_arrive = 0; __threadfence(); atomicAdd(&g_epoch, 1u); } \
            while (*(volatile unsigned*)&g_epoch - sE0 < nbar) { } \
            __threadfence(); \
        } \
        __syncthreads(); \
        nbar++; \
    } while (0)

    // ---------- phase 0: init bests + per-chunk histogram/ranks ----------
    for (int i = bx * 256 + tid; i < B; i += GRID * 256) { g_bestP[i] = 0ULL; g_bestN[i] = 0ULL; }
    int myRank = 0, myS = NS;
    if (bx < NC) {
        int i = bx * 256 + tid;
        if (i < B) { myS = sbj[i]; myS = min(max(myS, 0), NS - 1); }
        unsigned myMask = 0u; int cnt = 0;
        #pragma unroll
        for (int t2 = 0; t2 < NS; t2++) {
            unsigned m = __ballot_sync(full, myS == t2);
            if (myS == t2) myMask = m;
            if (lane == t2) cnt = __popc(m);
        }
        int rIW = __popc(myMask & ((1u << lane) - 1u));
        if (lane < NS) whist[w][lane] = cnt;
        __syncthreads();
        if (tid < NS) {
            int acc = 0;
            #pragma unroll
            for (int w2 = 0; w2 < 8; w2++) { woff[w2][tid] = acc; acc += whist[w2][tid]; }
            g_bhist[bx][tid] = acc;
        }
        __syncthreads();
        if (i < B && myS < NS) myRank = woff[w][myS] + rIW;
    }
    GBAR();

    // ---------- phase 1: global scan + scatter + tile list ----------
    if (bx < NC) {
        if (tid < NS) {
            int acc = 0, myoff = 0;
            for (int b = 0; b < NC; b++) { if (b == bx) myoff = acc; acc += g_bhist[b][tid]; }
            boffs[tid] = myoff; stot[tid] = acc;
        }
        __syncthreads();
        if (tid == 0) {
            int a = 0;
            for (int s = 0; s < NS; s++) { sbase[s] = a; a += stot[s]; }
            sbase[NS] = a;
        }
        __syncthreads();
        int i = bx * 256 + tid;
        if (i < B && myS < NS)
            g_order[sbase[myS] + boffs[myS] + myRank] = i;
        if (bx == 0) {
            if (tid == 0) {
                int acc = 0;
                for (int s = 0; s < NS; s++) {
                    int len = sbase[s + 1] - sbase[s];
                    int m = (len + 63) >> 6;
                    tb[s] = acc; tn[s] = m;
                    acc += m * (m + 1) / 2;
                }
                g_T = acc;
            }
            __syncthreads();
            for (int s = w; s < NS; s += 8) {
                int m = tn[s], lo = sbase[s], hi = sbase[s + 1];
                int ntri = m * (m + 1) / 2;
                for (int t = lane; t < ntri; t += 32) {
                    int a2 = 0, rem = t;
                    while (rem >= m - a2) { rem -= m - a2; a2++; }
                    int b2 = a2 + rem;
                    g_tiles[tb[s] + t] = make_int4(lo + 64 * a2, lo + 64 * b2, hi, 0);
                }
            }
        }
    }
    GBAR();

    // ---------- phase 2: mining (64x64 tiles, full triangle) ----------
    {
        const int tx = tid & 15, ty = tid >> 4;
        const int T = g_T;
        for (int t = bx; t < T; t += GRID) {
            const int4 dsc = g_tiles[t];
            const int aBase = dsc.x, bBase = dsc.y, hi = dsc.z;
            const int na = min(64, hi - aBase);
            const int nb = min(64, hi - bBase);

            __syncthreads();   // previous tile fully consumed
            if (tid < 64) {
                if (tid < na) { int i = g_order[aBase + tid]; aId[tid] = i; aLab[tid] = labels[i]; aSq[tid] = 0.f; }
                else { aId[tid] = -1; aLab[tid] = -2; aSq[tid] = PADSQ; }
            } else if (tid < 128) {
                int c = tid - 64;
                if (c < nb) { int j = g_order[bBase + c]; bId[c] = j; bLab[c] = labels[j]; bSq[c] = 0.f; }
                else { bId[c] = -1; bLab[c] = -3; bSq[c] = PADSQ; }
            } else if (tid < 192) {
                sPb[tid - 128] = 0ULL;
            } else {
                sNb[tid - 192] = 0ULL;
            }

            unsigned long long acc2[4][2];
            #pragma unroll
            for (int r = 0; r < 4; r++) { acc2[r][0] = 0ULL; acc2[r][1] = 0ULL; }

            for (int kh = 0; kh < D128; kh += KH) {
                __syncthreads();   // meta ready / prior chunk consumed
                // fill: lanes vary row (conflict-free scalar stores); kq = float4 idx 0..15
                #pragma unroll
                for (int it = 0; it < 4; it++) {
                    int idx = tid + it * 256;
                    int r = idx & 63, kq = idx >> 6;
                    float4 v = make_float4(0.f, 0.f, 0.f, 0.f);
                    float4 u = make_float4(0.f, 0.f, 0.f, 0.f);
                    int ia = aId[r], ib = bId[r];
                    if (ia >= 0) v = reinterpret_cast<const float4*>(emb + (size_t)ia * D128 + kh)[kq];
                    if (ib >= 0) u = reinterpret_cast<const float4*>(emb + (size_t)ib * D128 + kh)[kq];
                    int kb = kq * 4;
                    As[(kb + 0) * AP + r] = v.x;
                    As[(kb + 1) * AP + r] = v.y;
                    As[(kb + 2) * AP + r] = v.z;
                    As[(kb + 3) * AP + r] = v.w;
                    Bs[(kb + 0) * AP + r] = u.x;
                    Bs[(kb + 1) * AP + r] = u.y;
                    Bs[(kb + 2) * AP + r] = u.z;
                    Bs[(kb + 3) * AP + r] = u.w;
                }
                __syncthreads();

                // norms (warps 0-3) — overlaps the FMA loop of warps 4-7
                if (tid < 64) {
                    float s0 = 0.f, s1 = 0.f, s2 = 0.f, s3 = 0.f;
                    #pragma unroll
                    for (int k = 0; k < KH; k += 4) {
                        float v0 = As[(k + 0) * AP + tid]; s0 = fmaf(v0, v0, s0);
                        float v1 = As[(k + 1) * AP + tid]; s1 = fmaf(v1, v1, s1);
                        float v2 = As[(k + 2) * AP + tid]; s2 = fmaf(v2, v2, s2);
                        float v3 = As[(k + 3) * AP + tid]; s3 = fmaf(v3, v3, s3);
                    }
                    if (aId[tid] >= 0) aSq[tid] += (s0 + s1) + (s2 + s3);
                } else if (tid < 128) {
                    int c = tid - 64;
                    float s0 = 0.f, s1 = 0.f, s2 = 0.f, s3 = 0.f;
                    #pragma unroll
                    for (int k = 0; k < KH; k += 4) {
                        float v0 = Bs[(k + 0) * AP + c]; s0 = fmaf(v0, v0, s0);
                        float v1 = Bs[(k + 1) * AP + c]; s1 = fmaf(v1, v1, s1);
                        float v2 = Bs[(k + 2) * AP + c]; s2 = fmaf(v2, v2, s2);
                        float v3 = Bs[(k + 3) * AP + c]; s3 = fmaf(v3, v3, s3);
                    }
                    if (bId[c] >= 0) bSq[c] += (s0 + s1) + (s2 + s3);
                }

                #pragma unroll 8
                for (int k = 0; k < KH; k++) {
                    const float4 a0 = *reinterpret_cast<const float4*>(&As[k * AP + 4 * ty]);
                    const ulonglong2 bq = *reinterpret_cast<const ulonglong2*>(&Bs[k * AP + 4 * tx]);
                    unsigned long long aa0 = dup2(a0.x), aa1 = dup2(a0.y);
                    unsigned long long aa2 = dup2(a0.z), aa3 = dup2(a0.w);
                    FMA2(acc2[0][0], aa0, bq.x); FMA2(acc2[0][1], aa0, bq.y);
                    FMA2(acc2[1][0], aa1, bq.x); FMA2(acc2[1][1], aa1, bq.y);
                    FMA2(acc2[2][0], aa2, bq.x); FMA2(acc2[2][1], aa2, bq.y);
                    FMA2(acc2[3][0], aa3, bq.x); FMA2(acc2[3][1], aa3, bq.y);
                }
            }
            __syncthreads();   // norms final before selection

            int myBI[4], myBL[4]; float myBS[4];
            #pragma unroll
            for (int q = 0; q < 4; q++) {
                int cc = 4 * tx + q;
                myBI[q] = bId[cc]; myBL[q] = bLab[cc]; myBS[q] = bSq[cc];
            }
            unsigned long long colP[4], colN[4];
            #pragma unroll
            for (int q = 0; q < 4; q++) { colP[q] = 0ULL; colN[q] = 0ULL; }

            #pragma unroll
            for (int r = 0; r < 4; r++) {
                int rr = 4 * ty + r;
                int aI = aId[rr], aL = aLab[rr];
                float aS = aSq[rr];
                float af[2];
                unsigned long long rowP = 0ULL, rowN = 0ULL;
                #pragma unroll
                for (int p = 0; p < 2; p++) {
                    asm("mov.b64 {%0,%1}, %2;" : "=f"(af[0]), "=f"(af[1]) : "l"(acc2[r][p]));
                    #pragma unroll
                    for (int j = 0; j < 2; j++) {
                        int c = 2 * p + j;
                        float d2 = aS + myBS[c] - 2.f * af[j];
                        unsigned m = mono(d2);
                        if (aL == myBL[c]) {
                            if (aI != myBI[c]) {
                                unsigned long long kr = ((unsigned long long)m << 32) | (unsigned)(~myBI[c]);
                                unsigned long long kc = ((unsigned long long)m << 32) | (unsigned)(~aI);
                                if (kr > rowP) rowP = kr;
                                if (kc > colP[c]) colP[c] = kc;
                            }
                        } else {
                            unsigned long long kr = ((unsigned long long)(~m) << 32) | (unsigned)(~myBI[c]);
                            unsigned long long kc = ((unsigned long long)(~m) << 32) | (unsigned)(~aI);
                            if (kr > rowN) rowN = kr;
                            if (kc > colN[c]) colN[c] = kc;
                        }
                    }
                }
                // reduce across 16 tx (stays within half-warp)
                #pragma unroll
                for (int off = 1; off < 16; off <<= 1) {
                    unsigned long long oP = __shfl_xor_sync(full, rowP, off);
                    unsigned long long oN = __shfl_xor_sync(full, rowN, off);
                    if (oP > rowP) rowP = oP;
                    if (oN > rowN) rowN = oN;
                }
                if (tx == 0 && aI >= 0) {
                    if (rowP) atomicMax(&g_bestP[aI], rowP);
                    if (rowN) atomicMax(&g_bestN[aI], rowN);
                }
            }
            // col-side: combine the two ty values in this warp, then smem atomics
            #pragma unroll
            for (int q = 0; q < 4; q++) {
                unsigned long long oP = __shfl_xor_sync(full, colP[q], 16);
                unsigned long long oN = __shfl_xor_sync(full, colN[q], 16);
                if (oP > colP[q]) colP[q] = oP;
                if (oN > colN[q]) colN[q] = oN;
            }
            if (lane < 16) {
                #pragma unroll
                for (int q = 0; q < 4; q++) {
                    int cc = 4 * tx + q;
                    if (colP[q]) atomicMax(&sPb[cc], colP[q]);
                    if (colN[q]) atomicMax(&sNb[cc], colN[q]);
                }
            }
            __syncthreads();
            if (tid < 64) {
                int j = bId[tid];
                if (j >= 0) {
                    if (sPb[tid]) atomicMax(&g_bestP[j], sPb[tid]);
                    if (sNb[tid]) atomicMax(&g_bestN[j], sNb[tid]);
                }
            }
        }
    }
    GBAR();

    // ---------- phase 3: decode + triplet epilogue (all warps) ----------
    {
        float accL = 0.f, accV = 0.f;
        for (int i = bx * 8 + w; i < B; i += GRID * 8) {
            unsigned long long kp = g_bestP[i];
            unsigned long long kn = g_bestN[i];
            int bpI = kp ? (int)(~(unsigned)kp) : -1;
            int bnI = kn ? (int)(~(unsigned)kn) : -1;
            if (bpI >= 0 && bnI >= 0) {
                const float4 a = reinterpret_cast<const float4*>(emb + (size_t)i   * D128)[lane];
                const float4 p = reinterpret_cast<const float4*>(emb + (size_t)bpI * D128)[lane];
                const float4 n = reinterpret_cast<const float4*>(emb + (size_t)bnI * D128)[lane];
                float dx, sp, sn;
                dx = a.x - p.x + EPS; sp = dx * dx;
                dx = a.y - p.y + EPS; sp = fmaf(dx, dx, sp);
                dx = a.z - p.z + EPS; sp = fmaf(dx, dx, sp);
                dx = a.w - p.w + EPS; sp = fmaf(dx, dx, sp);
                dx = a.x - n.x + EPS; sn = dx * dx;
                dx = a.y - n.y + EPS; sn = fmaf(dx, dx, sn);
                dx = a.z - n.z + EPS; sn = fmaf(dx, dx, sn);
                dx = a.w - n.w + EPS; sn = fmaf(dx, dx, sn);
                #pragma unroll
                for (int off = 16; off > 0; off >>= 1) {
                    sp += __shfl_xor_sync(full, sp, off);
                    sn += __shfl_xor_sync(full, sn, off);
                }
                accL += fmaxf(sqrtf(sp) - sqrtf(sn) + MARGIN, 0.f);
                accV += 1.f;
            }
        }
        if (lane == 0) { sL[w] = accL; sV[w] = accV; }
        __syncthreads();
        if (tid == 0) {
            float l = 0.f, v = 0.f;
            #pragma unroll
            for (int q = 0; q < 8; q++) { l += sL[q]; v += sV[q]; }
            g_bL[bx] = l; g_bV[bx] = v;
        }
    }
    GBAR();

    // ---------- phase 4: final deterministic reduction (block 0) ----------
    if (bx == 0) {
        float l = 0.f, v = 0.f;
        for (int b = tid; b < GRID; b += 256) { l += g_bL[b]; v += g_bV[b]; }
        rl[tid] = l; rv[tid] = v;
        __syncthreads();
        for (int off = 128; off > 0; off >>= 1) {
            if (tid < off) { rl[tid] += rl[tid + off]; rv[tid] += rv[tid + off]; }
            __syncthreads();
        }
        if (tid == 0) {
            float cnt = rv[0];
            out[0] = (cnt > 0.f) ? (rl[0] / fmaxf(cnt, 1.f)) : 0.f;
        }
    }
}

extern "C" void kernel_launch(void* const* d_in, const int* in_sizes, int n_in,
                              void* d_out, int out_size) {
    const float* emb   = (const float*)d_in[0];
    const int* labels  = (const int*)d_in[1];
    const int* sbj     = (const int*)d_in[2];
    float* out = (float*)d_out;
    int B = in_sizes[1];

    k_all<<<GRID, 256>>>(emb, labels, sbj, out, B);
}